// round 12
// baseline (speedup 1.0000x reference)
#include <cuda_runtime.h>
#include <cuda_bf16.h>
#include <math.h>

// Fixed problem shape (from reference): B=128, S=2048, E=512, H=512.
#define MAX_B 128
#define MAX_S 2048
#define MAX_E 512
#define MAX_H 512
#define SPLITK 8
#define SETUP_BLOCKS 128

__device__ float g_c[MAX_B];                        // c[b] = q[b].bk
__device__ float g_sum[MAX_B];                      // row sums of exp
__device__ unsigned g_cnt[MAX_B];                   // per-batch completion count
__device__ unsigned g_bar;                          // monotonic grid barrier (never reset)
__device__ float g_part[SPLITK * MAX_B * MAX_H];    // q split-K partials
__device__ float g_part2[SPLITK * MAX_B * MAX_E];   // v split-K partials

// ---------------------------------------------------------------------------
// One 64x64 single-round split-K GEMM tile (device function).
// TRANSB=1: C = A @ Bm^T  (Bm [N,K] row-major).
// TRANSB=0/APART=1: A is a SPLITK-partial array; partials summed (+abias)
//           during the A load; bx==0 blocks accumulate c[m] += q[m,:].cw
//           into g_c via atomicAdd (tid<64).
// ---------------------------------------------------------------------------
template <int TRANSB, int APART>
__device__ __forceinline__ void gemm_tile(
    const float* __restrict__ A, const float* __restrict__ abias,
    const float* __restrict__ Bm, const float* __restrict__ cw,
    float* __restrict__ Cpart, int M, int N, int K,
    int bx, int by, int bz,
    float (*As)[68], float (*Bs)[68])
{
    int tid = threadIdx.x;
    int m0 = by * 64;
    int n0 = bx * 64;
    int kbeg = bz * 64;

    // ---- A strip: 64 x 64 = 1024 float4, 4 per thread ----
#pragma unroll
    for (int t = 0; t < 4; t++) {
        int idx = tid + t * 256;
        int r = idx >> 4;
        int kq = (idx & 15) * 4;
        size_t off = (size_t)(m0 + r) * K + kbeg + kq;
        float4 a;
        if (APART) {
            int MK = M * K;
            float4 s = *(const float4*)&abias[kbeg + kq];
#pragma unroll
            for (int p = 0; p < SPLITK; p++) {
                float4 pp = *(const float4*)&A[(size_t)p * MK + off];
                s.x += pp.x; s.y += pp.y; s.z += pp.z; s.w += pp.w;
            }
            a = s;
        } else {
            a = *(const float4*)&A[off];
        }
        *(float4*)&As[r][kq] = a;
    }

    // ---- B strip: 64 x 64 = 1024 float4, 4 per thread ----
    if (TRANSB) {
#pragma unroll
        for (int t = 0; t < 4; t++) {
            int idx = tid + t * 256;
            int n = idx >> 4;
            int kq = (idx & 15) * 4;
            float4 v = *(const float4*)&Bm[(size_t)(n0 + n) * K + kbeg + kq];
            Bs[kq][n] = v.x; Bs[kq + 1][n] = v.y; Bs[kq + 2][n] = v.z; Bs[kq + 3][n] = v.w;
        }
    } else {
#pragma unroll
        for (int t = 0; t < 4; t++) {
            int idx = tid + t * 256;
            int kk = idx >> 4;
            int nq = (idx & 15) * 4;
            *(float4*)&Bs[kk][nq] = *(const float4*)&Bm[(size_t)(kbeg + kk) * N + n0 + nq];
        }
    }
    __syncthreads();

    int tx = tid & 15;
    int ty = tid >> 4;
    float acc[4][4] = {};
#pragma unroll
    for (int kk = 0; kk < 64; kk++) {
        float a0 = As[ty * 4][kk];
        float a1 = As[ty * 4 + 1][kk];
        float a2 = As[ty * 4 + 2][kk];
        float a3 = As[ty * 4 + 3][kk];
        float4 bv = *(const float4*)&Bs[kk][tx * 4];
        acc[0][0] += a0 * bv.x; acc[0][1] += a0 * bv.y; acc[0][2] += a0 * bv.z; acc[0][3] += a0 * bv.w;
        acc[1][0] += a1 * bv.x; acc[1][1] += a1 * bv.y; acc[1][2] += a1 * bv.z; acc[1][3] += a1 * bv.w;
        acc[2][0] += a2 * bv.x; acc[2][1] += a2 * bv.y; acc[2][2] += a2 * bv.z; acc[2][3] += a2 * bv.w;
        acc[3][0] += a3 * bv.x; acc[3][1] += a3 * bv.y; acc[3][2] += a3 * bv.z; acc[3][3] += a3 * bv.w;
    }

#pragma unroll
    for (int r = 0; r < 4; r++) {
        float4 o = make_float4(acc[r][0], acc[r][1], acc[r][2], acc[r][3]);
        *(float4*)&Cpart[(size_t)bz * M * N + (size_t)(m0 + ty * 4 + r) * N + n0 + tx * 4] = o;
    }

    if (APART && bx == 0 && tid < 64) {
        float cpart = 0.0f;
#pragma unroll
        for (int kk = 0; kk < 64; kk++)
            cpart += As[tid][kk] * __ldg(&cw[kbeg + kk]);
        atomicAdd(&g_c[m0 + tid], cpart);
    }
}

// ---------------------------------------------------------------------------
// Fused setup: phase 1 = q partials (query @ Wq^T), grid barrier,
// phase 2 = v partials ((sum q + bq) @ Wk) + c accumulation.
// 128 blocks = one wave (co-resident, spin-safe). Barrier counter is
// monotonic across graph replays: each launch adds exactly 128.
// ---------------------------------------------------------------------------
__global__ __launch_bounds__(256) void setup_kernel(
    const float* __restrict__ query, const float* __restrict__ Wq,
    const float* __restrict__ bq, const float* __restrict__ Wk,
    const float* __restrict__ bk,
    float* __restrict__ part, float* __restrict__ part2,
    int B, int E, int H)
{
    __shared__ float As[64][68];
    __shared__ float Bs[64][68];
    int tid = threadIdx.x;
    int bid = blockIdx.x;
    int bx = bid & 7;          // 8 tiles along N (H or E = 512)
    int by = (bid >> 3) & 1;   // 2 tiles along M (B = 128)
    int bz = bid >> 4;         // SPLITK = 8

    // zero per-batch accumulators (before barrier, so phase 2 sees them)
    if (bid == 0 && tid < MAX_B) {
        g_c[tid] = 0.0f;
        g_sum[tid] = 0.0f;
        g_cnt[tid] = 0u;
    }

    // phase 1: q partials
    gemm_tile<1, 0>(query, nullptr, Wq, nullptr, part, B, H, E, bx, by, bz, As, Bs);

    // grid-wide barrier (release -> arrive -> spin -> acquire)
    __threadfence();
    __syncthreads();
    if (tid == 0) {
        unsigned t = atomicAdd(&g_bar, 1u);
        unsigned target = ((t >> 7) + 1u) << 7;   // (round+1)*128
        while (*(volatile unsigned*)&g_bar < target) { }
    }
    __syncthreads();
    __threadfence();

    // phase 2: v partials + c (reads part, L2-hot)
    gemm_tile<0, 1>(part, bq, Wk, bk, part2, B, E, H, bx, by, bz, As, Bs);
}

// ---------------------------------------------------------------------------
// Score + softmax: warp-per-row mask-skip with R3-style PAIRED rows.
// Per iteration: compute dots of 2 current rows, burst-prefetch the next 2
// (8 LDG.128), reduce both rows in one interleaved shfl sequence, emit both.
// Masked rows get 0 and their target data is never read.
// Last block per batch b normalizes the row. E fixed at 512.
// grid (S/256, B), 256 threads (8 warps); warp covers 32 consecutive rows.
// ---------------------------------------------------------------------------
__device__ __forceinline__ int poprow(unsigned& rem) {
    if (rem == 0) return -1;
    int r = __ffs(rem) - 1;
    rem &= rem - 1;
    return r;
}

__global__ __launch_bounds__(256, 3) void score_kernel(
    const float* __restrict__ target, const int* __restrict__ mask,
    float* __restrict__ out, int S)
{
    __shared__ bool lastdone;
    int b = blockIdx.y;
    int tid = threadIdx.x;
    int warp = tid >> 5;
    int lane = tid & 31;
    int sbase = blockIdx.x * 256 + warp * 32;

    // v[b] chunk for this lane: sum of 8 split-K partials, held in registers
    const int BE4 = MAX_B * MAX_E / 4;   // float4 stride between partials
    const float4* vp = reinterpret_cast<const float4*>(&g_part2[0]) + b * 128;
    float4 v0, v1, v2, v3;
#pragma unroll
    for (int j = 0; j < 4; j++) {
        float4 r = __ldg(vp + lane + 32 * j);
#pragma unroll
        for (int p = 1; p < SPLITK; p++) {
            float4 pp = __ldg(vp + p * BE4 + lane + 32 * j);
            r.x += pp.x; r.y += pp.y; r.z += pp.z; r.w += pp.w;
        }
        if (j == 0) v0 = r; else if (j == 1) v1 = r;
        else if (j == 2) v2 = r; else v3 = r;
    }
    float cb = g_c[b];

    const float4* tb = reinterpret_cast<const float4*>(target) +
                       ((size_t)b * S + sbase) * 128;
    const int* mrow = mask + (size_t)b * S;
    float* erow = out + (size_t)b * S;

    // mask ballot over this warp's 32 rows; masked rows -> 0 immediately
    bool keep = (mrow[sbase + lane] != 1);
    unsigned bits = __ballot_sync(0xffffffffu, keep);
    if (!keep) erow[sbase + lane] = 0.0f;

    float esum = 0.0f;

#define LOADROW(buf, r) { const float4* t_ = tb + (size_t)(r) * 128;            \
        buf[0] = __ldcs(t_ + lane);       buf[1] = __ldcs(t_ + lane + 32);      \
        buf[2] = __ldcs(t_ + lane + 64);  buf[3] = __ldcs(t_ + lane + 96); }

#define DOTV(buf, a) { a = buf[0].x * v0.x + buf[0].y * v0.y                    \
                         + buf[0].z * v0.z + buf[0].w * v0.w                    \
                         + buf[1].x * v1.x + buf[1].y * v1.y                    \
                         + buf[1].z * v1.z + buf[1].w * v1.w                    \
                         + buf[2].x * v2.x + buf[2].y * v2.y                    \
                         + buf[2].z * v2.z + buf[2].w * v2.w                    \
                         + buf[3].x * v3.x + buf[3].y * v3.y                    \
                         + buf[3].z * v3.z + buf[3].w * v3.w; }

    {
        unsigned rem = bits;
        float4 c0[4], c1[4], n0[4], n1[4];
        int r0 = poprow(rem);
        int r1 = poprow(rem);
        if (r0 >= 0) LOADROW(c0, r0);
        if (r1 >= 0) LOADROW(c1, r1);
        while (r0 >= 0) {
            int rn0 = poprow(rem);
            int rn1 = poprow(rem);

            float a0, a1;
            DOTV(c0, a0);
            if (r1 >= 0) { DOTV(c1, a1); } else a1 = 0.0f;

            if (rn0 >= 0) LOADROW(n0, rn0);
            if (rn1 >= 0) LOADROW(n1, rn1);

            // interleaved reduction of both rows
#pragma unroll
            for (int off = 16; off; off >>= 1) {
                a0 += __shfl_xor_sync(0xffffffffu, a0, off);
                a1 += __shfl_xor_sync(0xffffffffu, a1, off);
            }
            if (lane == 0) {
                float e0 = expf(10.0f * tanhf(a0 + cb) - 10.0f);
                erow[sbase + r0] = e0;
                esum += e0;
                if (r1 >= 0) {
                    float e1 = expf(10.0f * tanhf(a1 + cb) - 10.0f);
                    erow[sbase + r1] = e1;
                    esum += e1;
                }
            }

#pragma unroll
            for (int j = 0; j < 4; j++) { c0[j] = n0[j]; c1[j] = n1[j]; }
            r0 = rn0;
            r1 = rn1;
        }
    }

    if (lane == 0 && esum != 0.0f)
        atomicAdd(&g_sum[b], esum);

    __threadfence();
    __syncthreads();
    if (tid == 0) {
        unsigned t = atomicAdd(&g_cnt[b], 1u);
        lastdone = (t == gridDim.x - 1);
    }
    __syncthreads();

    if (lastdone) {
        __threadfence();
        float inv = 1.0f / g_sum[b];
        float4* rowv = reinterpret_cast<float4*>(out + (size_t)b * S);
        for (int i = tid; i < S / 4; i += 256) {
            float4 x = rowv[i];
            x.x *= inv; x.y *= inv; x.z *= inv; x.w *= inv;
            rowv[i] = x;
        }
    }
}

// ---------------------------------------------------------------------------
// Inputs (metadata order): query[B,E], target[B,S,E], mask[B,S],
//                          Wq[H,E], bq[H], Wk[H,E], bk[H]
// Output: alpha[B,S] float32
// ---------------------------------------------------------------------------
extern "C" void kernel_launch(void* const* d_in, const int* in_sizes, int n_in,
                              void* d_out, int out_size)
{
    const float* query  = (const float*)d_in[0];
    const float* target = (const float*)d_in[1];
    const int*   mask   = (const int*)d_in[2];
    const float* Wq     = (const float*)d_in[3];
    const float* bq     = (const float*)d_in[4];
    const float* Wk     = (const float*)d_in[5];
    const float* bk     = (const float*)d_in[6];
    float* out = (float*)d_out;

    int H = in_sizes[4];
    int E = in_sizes[1] / in_sizes[2];
    int B = in_sizes[0] / E;
    int S = in_sizes[2] / B;

    float* part_ptr; float* part2_ptr;
    cudaGetSymbolAddress((void**)&part_ptr, g_part);
    cudaGetSymbolAddress((void**)&part2_ptr, g_part2);

    // fused setup: q partials -> barrier -> v partials + c
    setup_kernel<<<SETUP_BLOCKS, 256>>>(query, Wq, bq, Wk, bk,
                                        part_ptr, part2_ptr, B, E, H);

    // fused score + softmax (mask-skip, paired-row pipeline, normalize)
    {
        dim3 grid(S / 256, B);
        score_kernel<<<grid, 256>>>(target, mask, out, S);
    }
}